// round 15
// baseline (speedup 1.0000x reference)
#include <cuda_runtime.h>
#include <cstdint>
#include <math.h>

#define Bnum 32
#define Tnum 2048
#define Hnum 512
#define CHUNK 32                    // t-rows per live chunk
#define NCHUNK (Tnum / CHUNK)       // 64 chunks per b (max)
#define ETHR 256                    // energy block threads (8 warps)
#define ROW4 (Hnum / 4)             // 128 float4 per row

// Scratch (static device arrays — allocation-free per harness rules)
__device__ __align__(16) float g_has[Bnum * Hnum];     // ha (unscaled)
__device__ __align__(16) float g_p[Bnum * Tnum];       // unnormalized numerators
__device__ __align__(16) float g_psum[Bnum * NCHUNK];  // per-(b,chunk) partials
__device__ unsigned g_done[Bnum];                      // zero-init; reset each use

__device__ __forceinline__ float ex2a(float x) {
    float y; asm("ex2.approx.f32 %0, %1;" : "=f"(y) : "f"(x)); return y;
}
__device__ __forceinline__ float tanha(float x) {
    float y; asm("tanh.approx.f32 %0, %1;" : "=f"(y) : "f"(x)); return y;
}

#define LOG2E 1.4426950408889634f

// ---------------------------------------------------------------------------
// Kernel A: ha[b,h] = sum_k mean_L(hidden)[b,k]*Wh[h,k] + bh[h].
// ---------------------------------------------------------------------------
__global__ __launch_bounds__(256) void proj_kernel(
    const float* __restrict__ hidden,
    const float* __restrict__ Wh,
    const float* __restrict__ bh)
{
    const int h0 = blockIdx.x * 8;
    __shared__ float s_w[8 * Hnum];   // 16KB
    {
        const float4* __restrict__ w4 = (const float4*)(Wh + (size_t)h0 * Hnum);
        for (int i = threadIdx.x; i < 8 * Hnum / 4; i += 256)
            ((float4*)s_w)[i] = w4[i];
    }
    __syncthreads();

    const int warp = threadIdx.x >> 5;
    const int lane = threadIdx.x & 31;
    const int b0 = warp * 4;
    const float* __restrict__ hA = hidden;                 // layer 0
    const float* __restrict__ hB = hidden + Bnum * Hnum;   // layer 1

    float acc[8][4];
    #pragma unroll
    for (int h = 0; h < 8; h++)
        #pragma unroll
        for (int j = 0; j < 4; j++) acc[h][j] = 0.f;

    #pragma unroll
    for (int k = lane; k < Hnum; k += 32) {
        float v0 = 0.5f * (hA[(b0 + 0) * Hnum + k] + hB[(b0 + 0) * Hnum + k]);
        float v1 = 0.5f * (hA[(b0 + 1) * Hnum + k] + hB[(b0 + 1) * Hnum + k]);
        float v2 = 0.5f * (hA[(b0 + 2) * Hnum + k] + hB[(b0 + 2) * Hnum + k]);
        float v3 = 0.5f * (hA[(b0 + 3) * Hnum + k] + hB[(b0 + 3) * Hnum + k]);
        #pragma unroll
        for (int h = 0; h < 8; h++) {
            float w = s_w[h * Hnum + k];
            acc[h][0] = fmaf(v0, w, acc[h][0]);
            acc[h][1] = fmaf(v1, w, acc[h][1]);
            acc[h][2] = fmaf(v2, w, acc[h][2]);
            acc[h][3] = fmaf(v3, w, acc[h][3]);
        }
    }
    #pragma unroll
    for (int h = 0; h < 8; h++)
        #pragma unroll
        for (int j = 0; j < 4; j++) {
            float a = acc[h][j];
            #pragma unroll
            for (int off = 16; off; off >>= 1)
                a += __shfl_xor_sync(0xffffffffu, a, off);
            acc[h][j] = a;
        }
    if (lane == 0) {
        #pragma unroll
        for (int h = 0; h < 8; h++) {
            float bhv = bh[h0 + h];
            #pragma unroll
            for (int j = 0; j < 4; j++)
                g_has[(b0 + j) * Hnum + h0 + h] = acc[h][j] + bhv;
        }
    }
}

// ---------------------------------------------------------------------------
// Kernel B: softmax numerators with fused normalization.
// KEY CHANGE vs R14: eo loads use DEFAULT cache policy (no __ldcs). The
// live working set (~64MB) fits in the 126MB L2, and L2 persists across
// graph replays -> steady-state reads are L2 hits (234c, not 577c DRAM).
// __ldcs (evict-first) had been discarding that reuse since R4.
// Warp's 4 rows processed as 2 interleaved pairs for load/compute overlap.
// Dense live-only scheduling + fused normalization retained.
// ---------------------------------------------------------------------------
__global__ __launch_bounds__(ETHR, 6) void energy_kernel(
    const float* __restrict__ eo,
    const float* __restrict__ Wo,
    const int*   __restrict__ enc_len_w,
    float* __restrict__ out)
{
    const int tid  = threadIdx.x;
    const int warp = tid >> 5;
    const int lane = tid & 31;

    // enc_len dtype auto-detect (JAX may canonicalize int64->int32):
    // lengths >= 1, so word[1]==0 iff buffer is little-endian int64.
    const bool is64 = (enc_len_w[1] == 0);

    // ---- per-warp dense work mapping (redundant across warps, L1-hot) ----
    const int len_l = is64 ? enc_len_w[2 * lane] : enc_len_w[lane];  // lane=b
    const int c_l = (len_l + CHUNK - 1) >> 5;       // live chunks for lane-b
    int p = c_l;                                    // inclusive prefix sum
    #pragma unroll
    for (int off = 1; off < 32; off <<= 1) {
        int n = __shfl_up_sync(0xffffffffu, p, off);
        if (lane >= off) p += n;
    }
    const int n_live = __shfl_sync(0xffffffffu, p, 31);
    const int i = blockIdx.x;
    if (i >= n_live) return;                        // dead block: retire now

    const unsigned m = __ballot_sync(0xffffffffu, p > i);
    const int b     = __ffs(m) - 1;
    const int chunk = i - (__shfl_sync(0xffffffffu, p, b) -
                           __shfl_sync(0xffffffffu, c_l, b));
    const int len   = __shfl_sync(0xffffffffu, len_l, b);
    const int cb    = __shfl_sync(0xffffffffu, c_l, b);
    const int tbase = chunk * CHUNK;

    __shared__ __align__(16) float s_has[Hnum];
    __shared__ __align__(16) float s_wo[Hnum];
    __shared__ float s_ws[8];
    __shared__ float s_red[2];
    __shared__ float s_rinv;
    __shared__ int   s_last;

    for (int k = tid; k < Hnum / 4; k += ETHR) {
        ((float4*)s_has)[k] = ((const float4*)(g_has + b * Hnum))[k];
        ((float4*)s_wo)[k]  = ((const float4*)Wo)[k];
    }
    __syncthreads();

    const float4* __restrict__ eo4 = (const float4*)eo;
    const size_t ts = (size_t)Bnum * ROW4;          // t-stride in float4
    float wsum = 0.f;

    #pragma unroll
    for (int rr = 0; rr < 2; rr++) {                // 2 pairs of rows
        const int t0 = tbase + warp * 4 + rr * 2;
        const int nv = min(2, max(0, len - t0));    // valid rows in pair
        if (nv > 0) {
            const size_t base = ((size_t)t0 * Bnum + b) * ROW4 + lane;
            float accA = 0.f, accB = 0.f;
            if (nv == 2) {
                #pragma unroll
                for (int j = 0; j < 4; j++) {
                    const int k = j * 32 + lane;
                    float4 eA = eo4[base + (size_t)j * 32];
                    float4 eB = eo4[base + ts + (size_t)j * 32];
                    float4 hs = ((const float4*)s_has)[k];
                    float4 w  = ((const float4*)s_wo)[k];
                    accA = fmaf(tanha(eA.x + hs.x), w.x, accA);
                    accB = fmaf(tanha(eB.x + hs.x), w.x, accB);
                    accA = fmaf(tanha(eA.y + hs.y), w.y, accA);
                    accB = fmaf(tanha(eB.y + hs.y), w.y, accB);
                    accA = fmaf(tanha(eA.z + hs.z), w.z, accA);
                    accB = fmaf(tanha(eB.z + hs.z), w.z, accB);
                    accA = fmaf(tanha(eA.w + hs.w), w.w, accA);
                    accB = fmaf(tanha(eB.w + hs.w), w.w, accB);
                }
            } else {   // nv == 1
                #pragma unroll
                for (int j = 0; j < 4; j++) {
                    const int k = j * 32 + lane;
                    float4 eA = eo4[base + (size_t)j * 32];
                    float4 hs = ((const float4*)s_has)[k];
                    float4 w  = ((const float4*)s_wo)[k];
                    accA = fmaf(tanha(eA.x + hs.x), w.x, accA);
                    accA = fmaf(tanha(eA.y + hs.y), w.y, accA);
                    accA = fmaf(tanha(eA.z + hs.z), w.z, accA);
                    accA = fmaf(tanha(eA.w + hs.w), w.w, accA);
                }
            }
            #pragma unroll
            for (int off = 16; off; off >>= 1) {
                accA += __shfl_xor_sync(0xffffffffu, accA, off);
                accB += __shfl_xor_sync(0xffffffffu, accB, off);
            }
            if (lane == 0) {
                // no-max exp is safe: |energy| <= sum|Wo| ~ 18 << fp32 range
                float pA = ex2a(accA * LOG2E);
                g_p[b * Tnum + t0] = pA;
                wsum += pA;
                if (nv == 2) {
                    float pB = ex2a(accB * LOG2E);
                    g_p[b * Tnum + t0 + 1] = pB;
                    wsum += pB;
                }
            }
        }
    }
    if (lane == 0) s_ws[warp] = wsum;
    __syncthreads();
    if (tid == 0) {
        float tot = 0.f;
        #pragma unroll
        for (int k = 0; k < 8; k++) tot += s_ws[k];
        g_psum[b * NCHUNK + chunk] = tot;
    }

    // ---- threadfence-reduction handoff: last live block of b normalizes ----
    __threadfence();
    if (tid == 0)
        s_last = (atomicAdd(&g_done[b], 1u) == (unsigned)(cb - 1));
    __syncthreads();
    if (!s_last) return;

    if (tid < 64) {
        float v = (tid < cb) ? g_psum[b * NCHUNK + tid] : 0.f;
        #pragma unroll
        for (int off = 16; off; off >>= 1)
            v += __shfl_xor_sync(0xffffffffu, v, off);
        if (lane == 0) s_red[tid >> 5] = v;
    }
    __syncthreads();
    if (tid == 0) s_rinv = 1.0f / (s_red[0] + s_red[1]);
    __syncthreads();
    const float rinv = s_rinv;

    // out[b,t] = p*rinv for t<len, 0 otherwise (masked tail zeroed here)
    float4* __restrict__ o4 = (float4*)&out[b * Tnum];
    const float* __restrict__ prow = &g_p[b * Tnum];
    #pragma unroll
    for (int q = tid; q < Tnum / 4; q += ETHR) {
        const int t0 = q * 4;
        float4 o = make_float4(0.f, 0.f, 0.f, 0.f);
        if (t0 + 3 < len) {
            float4 pv = ((const float4*)prow)[q];
            o.x = pv.x * rinv; o.y = pv.y * rinv;
            o.z = pv.z * rinv; o.w = pv.w * rinv;
        } else if (t0 < len) {
            if (t0 + 0 < len) o.x = prow[t0 + 0] * rinv;
            if (t0 + 1 < len) o.y = prow[t0 + 1] * rinv;
            if (t0 + 2 < len) o.z = prow[t0 + 2] * rinv;
            if (t0 + 3 < len) o.w = prow[t0 + 3] * rinv;
        }
        o4[q] = o;
    }
    if (tid == 0) g_done[b] = 0u;   // reset for next graph replay
}

// ---------------------------------------------------------------------------
extern "C" void kernel_launch(void* const* d_in, const int* in_sizes, int n_in,
                              void* d_out, int out_size)
{
    const float* hidden  = (const float*)d_in[0];      // [L,B,H]
    const float* eo      = (const float*)d_in[1];      // [T,B,H]
    const int*   enc_len = (const int*)d_in[2];        // [B] int32/int64 (auto-detect)
    const float* Wh      = (const float*)d_in[3];      // [H,H]
    const float* bh      = (const float*)d_in[4];      // [H]
    const float* Wo      = (const float*)d_in[5];      // [1,H]
    // d_in[6] = bo: uniform additive constant -> cancels in softmax, unused.
    float* out = (float*)d_out;                         // [B,T,1]

    proj_kernel<<<Hnum / 8, 256>>>(hidden, Wh, bh);
    energy_kernel<<<Bnum * NCHUNK, ETHR>>>(eo, Wo, enc_len, out);
}

// round 16
// speedup vs baseline: 1.1143x; 1.1143x over previous
#include <cuda_runtime.h>
#include <cstdint>
#include <math.h>

#define Bnum 32
#define Tnum 2048
#define Hnum 512
#define CHUNK 32                    // t-rows per chunk
#define NCHUNK (Tnum / CHUNK)       // 64 chunks per b
#define ETHR 256                    // 8 warps
#define ROW4 (Hnum / 4)             // 128 float4 per row
#define NPROJ 256                   // proj-role blocks (32 b x 8 h-slices)

// Scratch (static device arrays — allocation-free per harness rules)
__device__ __align__(16) float g_has[Bnum * Hnum];     // ha (unscaled)
__device__ __align__(16) float g_p[Bnum * Tnum];       // unnormalized numerators
__device__ __align__(16) float g_psum[Bnum * NCHUNK];  // per-(b,chunk) partials
__device__ unsigned g_done[Bnum];    // chunk-completion counters (reset per use)
__device__ unsigned g_pdone[Bnum];   // proj-slice counters (reset per use)
__device__ unsigned g_ready[Bnum];   // ha[b,:] ready flags (reset per use)

__device__ __forceinline__ float ex2a(float x) {
    float y; asm("ex2.approx.f32 %0, %1;" : "=f"(y) : "f"(x)); return y;
}
__device__ __forceinline__ float tanha(float x) {
    float y; asm("tanh.approx.f32 %0, %1;" : "=f"(y) : "f"(x)); return y;
}

#define LOG2E 1.4426950408889634f

// ---------------------------------------------------------------------------
// ONE kernel. Phase P (bids 0..255): compute ha[pb, h0..h0+63] and release
// per-b ready flags. Phase S (all blocks): stream eo for (b,chunk), spinning
// briefly on g_ready[b] first (producers are guaranteed co-resident: wave-1
// holds ~1184 blocks >= 256 at 8 blocks/SM). Fused normalization via the
// threadfence-reduction "last block of b" pattern, which also resets all
// flags for the next graph replay.
// ---------------------------------------------------------------------------
__global__ __launch_bounds__(ETHR, 8) void fused_kernel(
    const float* __restrict__ hidden,    // [2,B,H]
    const float* __restrict__ eo,        // [T,B,H]
    const int*   __restrict__ enc_len_w, // [B] int32/int64 (auto-detect)
    const float* __restrict__ Wh,        // [H,H]
    const float* __restrict__ bh,        // [H]
    const float* __restrict__ Wo,        // [1,H]
    float* __restrict__ out)             // [B,T,1]
{
    const int tid  = threadIdx.x;
    const int warp = tid >> 5;
    const int lane = tid & 31;
    const int chunk = blockIdx.x;                 // 0..63
    const int b     = blockIdx.y;                 // 0..31
    const int bid   = chunk + NCHUNK * b;

    __shared__ __align__(16) float s_hm[Hnum];    // proj: mean(hidden[pb])
    __shared__ __align__(16) float s_has[Hnum];
    __shared__ __align__(16) float s_wo[Hnum];
    __shared__ float s_ws[8];
    __shared__ float s_red[2];
    __shared__ float s_rinv;
    __shared__ int   s_last;

    // ================= Phase P: projection (first 256 bids) =================
    if (bid < NPROJ) {
        const int pb = bid >> 3;                  // 0..31
        const int h0 = (bid & 7) * 64;            // 0,64,...,448
        if (tid < ROW4) {
            float4 a = ((const float4*)(hidden + (size_t)pb * Hnum))[tid];
            float4 c = ((const float4*)(hidden + (size_t)(Bnum + pb) * Hnum))[tid];
            float4 r;
            r.x = 0.5f * (a.x + c.x); r.y = 0.5f * (a.y + c.y);
            r.z = 0.5f * (a.z + c.z); r.w = 0.5f * (a.w + c.w);
            ((float4*)s_hm)[tid] = r;
        }
        __syncthreads();
        #pragma unroll
        for (int it = 0; it < 8; it++) {          // warp handles one h per iter
            const int h = h0 + it * 8 + warp;
            const float4* __restrict__ w4 = (const float4*)(Wh + (size_t)h * Hnum);
            float acc = 0.f;
            #pragma unroll
            for (int i = 0; i < 4; i++) {
                const int k = i * 32 + lane;
                float4 w = w4[k];
                float4 m = ((const float4*)s_hm)[k];
                acc = fmaf(m.x, w.x, acc);
                acc = fmaf(m.y, w.y, acc);
                acc = fmaf(m.z, w.z, acc);
                acc = fmaf(m.w, w.w, acc);
            }
            #pragma unroll
            for (int off = 16; off; off >>= 1)
                acc += __shfl_xor_sync(0xffffffffu, acc, off);
            if (lane == 0)
                g_has[pb * Hnum + h] = acc + bh[h];
        }
        __threadfence();                          // publish g_has slice
        __syncthreads();
        if (tid == 0) {
            if (atomicAdd(&g_pdone[pb], 1u) == 7u)
                atomicExch(&g_ready[pb], 1u);     // 8th slice: release b
        }
    }

    // ===================== Phase S: energy streaming ========================
    // enc_len dtype auto-detect (JAX may canonicalize int64->int32):
    // lengths >= 1, so word[1]==0 iff buffer is little-endian int64.
    const bool is64 = (enc_len_w[1] == 0);
    const int len = is64 ? enc_len_w[2 * b] : enc_len_w[b];
    const int tbase = chunk * CHUNK;

    if (tbase < len) {
        if (tid == 0) {                           // wait for ha[b,:]
            while (atomicAdd(&g_ready[b], 0u) == 0u) __nanosleep(128);
        }
        __syncthreads();

        for (int k = tid; k < ROW4; k += ETHR) {
            ((float4*)s_has)[k] = ((const float4*)(g_has + b * Hnum))[k];
            ((float4*)s_wo)[k]  = ((const float4*)Wo)[k];
        }
        __syncthreads();

        const float4* __restrict__ eo4 = (const float4*)eo;
        float wsum = 0.f;
        #pragma unroll
        for (int r = 0; r < CHUNK / 8; r++) {     // warp owns 4 rows
            const int t = tbase + warp * (CHUNK / 8) + r;
            if (t < len) {
                const size_t base = ((size_t)t * Bnum + b) * ROW4;
                float acc = 0.f;
                #pragma unroll
                for (int j = 0; j < 4; j++) {
                    const int k = j * 32 + lane;
                    float4 e  = __ldcs(&eo4[base + k]);
                    float4 hs = ((const float4*)s_has)[k];
                    float4 w  = ((const float4*)s_wo)[k];
                    acc = fmaf(tanha(e.x + hs.x), w.x, acc);
                    acc = fmaf(tanha(e.y + hs.y), w.y, acc);
                    acc = fmaf(tanha(e.z + hs.z), w.z, acc);
                    acc = fmaf(tanha(e.w + hs.w), w.w, acc);
                }
                #pragma unroll
                for (int off = 16; off; off >>= 1)
                    acc += __shfl_xor_sync(0xffffffffu, acc, off);
                if (lane == 0) {
                    // no-max exp is safe: |energy| <= sum|Wo| ~ 18 << fp32 range
                    float pv = ex2a(acc * LOG2E);
                    g_p[b * Tnum + t] = pv;
                    wsum += pv;
                }
            } else if (lane == 0) {
                g_p[b * Tnum + t] = 0.f;
            }
        }
        if (lane == 0) s_ws[warp] = wsum;
        __syncthreads();
        if (tid == 0) {
            float tot = 0.f;
            #pragma unroll
            for (int k = 0; k < 8; k++) tot += s_ws[k];
            g_psum[b * NCHUNK + chunk] = tot;
        }
    } else {
        // fully masked chunk: zeros, no eo traffic, no spin
        if (tid < CHUNK / 4)
            ((float4*)&g_p[b * Tnum + tbase])[tid] = make_float4(0.f, 0.f, 0.f, 0.f);
        if (tid == 0) g_psum[b * NCHUNK + chunk] = 0.f;
    }

    // ---- threadfence-reduction handoff: last block of this b normalizes ----
    __threadfence();
    if (tid == 0)
        s_last = (atomicAdd(&g_done[b], 1u) == NCHUNK - 1);
    __syncthreads();
    if (!s_last) return;

    if (tid < 64) {
        float v = g_psum[b * NCHUNK + tid];       // 64 partials
        #pragma unroll
        for (int off = 16; off; off >>= 1)
            v += __shfl_xor_sync(0xffffffffu, v, off);
        if (lane == 0) s_red[tid >> 5] = v;
    }
    __syncthreads();
    if (tid == 0) s_rinv = 1.0f / (s_red[0] + s_red[1]);
    __syncthreads();
    const float rinv = s_rinv;

    const float4* __restrict__ p4 = (const float4*)&g_p[b * Tnum];
    float4* __restrict__ o4 = (float4*)&out[b * Tnum];
    #pragma unroll
    for (int i = tid; i < Tnum / 4; i += ETHR) {
        float4 p = p4[i];
        float4 o;
        o.x = p.x * rinv; o.y = p.y * rinv; o.z = p.z * rinv; o.w = p.w * rinv;
        o4[i] = o;
    }
    if (tid == 0) {                               // reset for next graph replay
        g_done[b]  = 0u;
        g_pdone[b] = 0u;
        g_ready[b] = 0u;
    }
}

// ---------------------------------------------------------------------------
extern "C" void kernel_launch(void* const* d_in, const int* in_sizes, int n_in,
                              void* d_out, int out_size)
{
    const float* hidden  = (const float*)d_in[0];      // [L,B,H]
    const float* eo      = (const float*)d_in[1];      // [T,B,H]
    const int*   enc_len = (const int*)d_in[2];        // [B] int32/int64 (auto-detect)
    const float* Wh      = (const float*)d_in[3];      // [H,H]
    const float* bh      = (const float*)d_in[4];      // [H]
    const float* Wo      = (const float*)d_in[5];      // [1,H]
    // d_in[6] = bo: uniform additive constant -> cancels in softmax, unused.
    float* out = (float*)d_out;                         // [B,T,1]

    fused_kernel<<<dim3(NCHUNK, Bnum), ETHR>>>(hidden, eo, enc_len, Wh, bh, Wo, out);
}